// round 1
// baseline (speedup 1.0000x reference)
#include <cuda_runtime.h>

#define NN 512
#define XD 64
#define HD 128

// Dynamic SMEM layout (float offsets):
//  W1s  [64][128]      @ 0      (8192)
//  W2s  [128][128]     @ 8192   (16384)
//  U    (union)        @ 24576  (16896)
//     ys   [128][68]   @ U       (8704)
//     DT   [64][128]   @ U+8704  (8192)
//     H1T  [128][132]  @ U       (16896)   -- written after GEMM1 finishes
//  tvs  [128]          @ 41472
//  b2s  [128]          @ 41600
//  w3s  [128]          @ 41728
//  xs   [64]           @ 41856
//  red  [16][132]      @ 41920  (2112)
// total 44032 floats = 176128 bytes
#define SMEM_FLOATS 44032

__global__ void __launch_bounds__(256, 1)
pairmlp_kernel(const float* __restrict__ x, const float* __restrict__ y,
               const float* __restrict__ t, const float* __restrict__ W1,
               const float* __restrict__ b1, const float* __restrict__ W2,
               const float* __restrict__ b2, const float* __restrict__ W3,
               const float* __restrict__ b3, float* __restrict__ out)
{
    extern __shared__ float s[];
    float* W1s = s;
    float* W2s = s + 8192;
    float* U   = s + 24576;
    float* ys  = U;            // [128][68] padded
    float* DT  = U + 8704;     // [64][128]
    float* H1T = U;            // [128][132] padded (aliases ys+DT after sync)
    float* tvs = s + 41472;
    float* b2s = s + 41600;
    float* w3s = s + 41728;
    float* xs  = s + 41856;
    float* red = s + 41920;    // [16][132]

    const int tid = threadIdx.x;
    const int b  = blockIdx.z;
    const int i  = blockIdx.y;
    const int j0 = blockIdx.x * 128;

    // ---- stage weights ----
    for (int idx = tid; idx < 64 * 128; idx += 256) W1s[idx] = W1[idx];
    for (int idx = tid; idx < 128 * 128; idx += 256) W2s[idx] = W2[idx];
    if (tid < 128) { b2s[tid] = b2[tid]; w3s[tid] = W3[tid]; }
    if (tid < 64)  xs[tid] = x[((size_t)(b * NN + i)) * XD + tid];

    // tv[h] = b1[h] + sum_d t[b,d] * W1[64+d, h]
    if (tid < 128) {
        float sum = b1[tid];
        #pragma unroll
        for (int d = 0; d < 32; d++)
            sum += t[b * 32 + d] * W1[(64 + d) * 128 + tid];
        tvs[tid] = sum;
    }

    // ---- stage y tile [128][64] -> ys (stride 68) ----
    {
        const float4* yg = (const float4*)(y + ((size_t)(b * NN + j0)) * XD);
        for (int idx = tid; idx < 128 * 16; idx += 256) {
            int r = idx >> 4, g = idx & 15;
            float4 v = yg[r * 16 + g];
            float* dst = ys + r * 68 + g * 4;
            dst[0] = v.x; dst[1] = v.y; dst[2] = v.z; dst[3] = v.w;
        }
    }
    __syncthreads();

    // ---- DiffT[k][r] = (x_i[k] - y_j[k])^2 ----
    for (int idx = tid; idx < 64 * 128; idx += 256) {
        int r = idx & 127, k = idx >> 7;
        float d = xs[k] - ys[r * 68 + k];
        DT[k * 128 + r] = d * d;
    }
    __syncthreads();

    const int ty = tid >> 4, tx = tid & 15;
    const int r0 = ty * 8, c0 = tx * 8;

    float acc[8][8];
    #pragma unroll
    for (int a = 0; a < 8; a++)
        #pragma unroll
        for (int c = 0; c < 8; c++) acc[a][c] = 0.f;

    // ---- GEMM1: C1[r][h] = sum_k DT[k][r] * W1s[k][h] ----
    #pragma unroll 2
    for (int k = 0; k < 64; k++) {
        float a[8], w[8];
        const float4* ap = (const float4*)(DT + k * 128 + r0);
        float4 a0 = ap[0], a1 = ap[1];
        a[0]=a0.x; a[1]=a0.y; a[2]=a0.z; a[3]=a0.w;
        a[4]=a1.x; a[5]=a1.y; a[6]=a1.z; a[7]=a1.w;
        const float4* wp = (const float4*)(W1s + k * 128 + c0);
        float4 w0 = wp[0], w1 = wp[1];
        w[0]=w0.x; w[1]=w0.y; w[2]=w0.z; w[3]=w0.w;
        w[4]=w1.x; w[5]=w1.y; w[6]=w1.z; w[7]=w1.w;
        #pragma unroll
        for (int rr = 0; rr < 8; rr++)
            #pragma unroll
            for (int cc = 0; cc < 8; cc++)
                acc[rr][cc] += a[rr] * w[cc];
    }
    __syncthreads();   // everyone done reading DT before H1T overwrites union

    // ---- ReLU(+tv) and transpose into H1T[h][r] (stride 132) ----
    #pragma unroll
    for (int cc = 0; cc < 8; cc++) {
        int h = c0 + cc;
        float tvh = tvs[h];
        #pragma unroll
        for (int rr = 0; rr < 8; rr++) {
            float v = acc[rr][cc] + tvh;
            H1T[h * 132 + r0 + rr] = v > 0.f ? v : 0.f;
            acc[rr][cc] = 0.f;
        }
    }
    __syncthreads();

    // ---- GEMM2: C2[r][n] = sum_h H1T[h][r] * W2s[h][n] ----
    #pragma unroll 2
    for (int h = 0; h < 128; h++) {
        float a[8], w[8];
        const float4* ap = (const float4*)(H1T + h * 132 + r0);
        float4 a0 = ap[0], a1 = ap[1];
        a[0]=a0.x; a[1]=a0.y; a[2]=a0.z; a[3]=a0.w;
        a[4]=a1.x; a[5]=a1.y; a[6]=a1.z; a[7]=a1.w;
        const float4* wp = (const float4*)(W2s + h * 128 + c0);
        float4 w0 = wp[0], w1 = wp[1];
        w[0]=w0.x; w[1]=w0.y; w[2]=w0.z; w[3]=w0.w;
        w[4]=w1.x; w[5]=w1.y; w[6]=w1.z; w[7]=w1.w;
        #pragma unroll
        for (int rr = 0; rr < 8; rr++)
            #pragma unroll
            for (int cc = 0; cc < 8; cc++)
                acc[rr][cc] += a[rr] * w[cc];
    }

    // ---- fused ReLU * W3, partial reduce over this thread's 8 neurons ----
    float part[8];
    #pragma unroll
    for (int rr = 0; rr < 8; rr++) part[rr] = 0.f;
    #pragma unroll
    for (int cc = 0; cc < 8; cc++) {
        int n = c0 + cc;
        float bn = b2s[n], w3 = w3s[n];
        #pragma unroll
        for (int rr = 0; rr < 8; rr++) {
            float v = acc[rr][cc] + bn;
            if (v > 0.f) part[rr] += v * w3;
        }
    }
    #pragma unroll
    for (int rr = 0; rr < 8; rr++)
        red[tx * 132 + r0 + rr] = part[rr];
    __syncthreads();

    // ---- cross-thread reduce + store ----
    if (tid < 128) {
        float sum = b3[0];
        #pragma unroll
        for (int tt = 0; tt < 16; tt++)
            sum += red[tt * 132 + tid];
        out[((size_t)(b * NN + i)) * NN + j0 + tid] = sum;
    }
}

extern "C" void kernel_launch(void* const* d_in, const int* in_sizes, int n_in,
                              void* d_out, int out_size)
{
    const float* x  = (const float*)d_in[0];
    const float* y  = (const float*)d_in[1];
    const float* t  = (const float*)d_in[2];
    const float* W1 = (const float*)d_in[3];
    const float* b1 = (const float*)d_in[4];
    const float* W2 = (const float*)d_in[5];
    const float* b2 = (const float*)d_in[6];
    const float* W3 = (const float*)d_in[7];
    const float* b3 = (const float*)d_in[8];
    float* out = (float*)d_out;

    const int smem_bytes = SMEM_FLOATS * sizeof(float);
    cudaFuncSetAttribute(pairmlp_kernel,
                         cudaFuncAttributeMaxDynamicSharedMemorySize, smem_bytes);

    dim3 grid(NN / 128, NN, 4);  // (j-tiles, i, b)
    pairmlp_kernel<<<grid, 256, smem_bytes>>>(x, y, t, W1, b1, W2, b2, W3, b3, out);
}

// round 3
// speedup vs baseline: 4.3310x; 4.3310x over previous
#include <cuda_runtime.h>
#include <cstdint>

#define NN 512
#define GRID 148
#define TPB 256
#define TILES 8192

// ---- SMEM float offsets ----
#define OFF_W1T 0       // W1^T [n=128][k=64]  stride 68  -> 8704
#define OFF_W2T 8704    // W2^T [n=128][h=128] stride 132 -> 16896
#define OFF_YS  25600   // y tile [128][64]    stride 68  -> 8704
#define OFF_DH  34304   // D/H union [128][132]           -> 16896
#define OFF_TV  51200   // tv[4][128]
#define OFF_B2S 51712
#define OFF_W3S 51840
#define SMEM_FLOATS 51968   // 207872 bytes

__device__ __forceinline__ uint32_t cvt_tf32(float f) {
    uint32_t u; asm("cvt.rna.tf32.f32 %0, %1;" : "=r"(u) : "f"(f)); return u;
}
__device__ __forceinline__ uint32_t smem_u32(const void* p) {
    uint32_t a;
    asm("{ .reg .u64 t; cvta.to.shared.u64 t, %1; cvt.u32.u64 %0, t; }" : "=r"(a) : "l"(p));
    return a;
}
__device__ __forceinline__ void ldsm_x4(uint32_t& r0, uint32_t& r1, uint32_t& r2, uint32_t& r3,
                                        uint32_t addr) {
    asm volatile("ldmatrix.sync.aligned.m8n8.x4.shared.b16 {%0,%1,%2,%3}, [%4];"
                 : "=r"(r0), "=r"(r1), "=r"(r2), "=r"(r3) : "r"(addr));
}
__device__ __forceinline__ void mma_tf32(float* c,
                                         uint32_t a0, uint32_t a1, uint32_t a2, uint32_t a3,
                                         uint32_t b0, uint32_t b1) {
    asm volatile("mma.sync.aligned.m16n8k8.row.col.f32.tf32.tf32.f32 "
                 "{%0,%1,%2,%3},{%4,%5,%6,%7},{%8,%9},{%0,%1,%2,%3};"
                 : "+f"(c[0]), "+f"(c[1]), "+f"(c[2]), "+f"(c[3])
                 : "r"(a0), "r"(a1), "r"(a2), "r"(a3), "r"(b0), "r"(b1));
}

__global__ void __launch_bounds__(TPB, 1)
pairmlp_mma(const float* __restrict__ x, const float* __restrict__ y,
            const float* __restrict__ t, const float* __restrict__ W1,
            const float* __restrict__ b1, const float* __restrict__ W2,
            const float* __restrict__ b2, const float* __restrict__ W3,
            const float* __restrict__ b3, float* __restrict__ out)
{
    extern __shared__ float s[];
    const int tid = threadIdx.x;
    const int wid = tid >> 5;
    const int l   = tid & 31;
    const int m16 = wid * 16;
    const uint32_t sb = smem_u32(s);

    // ---- one-time staging ----
    // W1T[n][k] = tf32(W1[k][n]); coalesced LDG
    for (int idx = tid; idx < 64 * 128; idx += TPB) {
        int k = idx >> 7, n = idx & 127;
        ((uint32_t*)s)[OFF_W1T + n * 68 + k] = cvt_tf32(W1[k * 128 + n]);
    }
    // W2T[n][h] = tf32(W2[h][n])
    for (int idx = tid; idx < 128 * 128; idx += TPB) {
        int h = idx >> 7, n = idx & 127;
        ((uint32_t*)s)[OFF_W2T + n * 132 + h] = cvt_tf32(W2[h * 128 + n]);
    }
    // tv[b][h] = b1[h] + t[b]·W1[64:,h]
    for (int idx = tid; idx < 4 * 128; idx += TPB) {
        int bb = idx >> 7, h = idx & 127;
        float sum = b1[h];
        #pragma unroll
        for (int d = 0; d < 32; d++) sum += t[bb * 32 + d] * W1[(64 + d) * 128 + h];
        s[OFF_TV + idx] = sum;
    }
    if (tid < 128) { s[OFF_B2S + tid] = b2[tid]; s[OFF_W3S + tid] = W3[tid]; }
    const float b3v = b3[0];
    __syncthreads();

    // ---- per-lane ldmatrix base addresses (bytes) ----
    const int g = l >> 3, r = l & 7;
    // A fragment (16x8): m0 rows0-7/k0-3, m1 rows8-15/k0-3, m2 rows0-7/k4-7, m3 rows8-15/k4-7
    const uint32_t aRow = (uint32_t)(m16 + (g & 1) * 8 + r);
    const uint32_t aA   = sb + (OFF_DH + aRow * 132) * 4 + (uint32_t)(g >> 1) * 16;
    // B fragment pair: m0 (n0..7,k0), m1 (n0..7,k0+4), m2 (n0+8..15,k0), m3 (n0+8..15,k0+4)
    const uint32_t bn  = (uint32_t)((g >> 1) * 8 + r);
    const uint32_t bCb = (uint32_t)(g & 1) * 16;
    const uint32_t bB1 = sb + (OFF_W1T + bn * 68) * 4 + bCb;
    const uint32_t bB2 = sb + (OFF_W2T + bn * 132) * 4 + bCb;

    const int start = (TILES * blockIdx.x) / GRID;
    const int end   = (TILES * (blockIdx.x + 1)) / GRID;
    int cur_bjt = -1;

    const int qr = l >> 2;        // quad row 0..7
    const int qc = l & 3;         // quad col 0..3

    for (int tau = start; tau < end; ++tau) {
        const int b  = tau >> 11;
        const int jt = (tau >> 9) & 3;
        const int i  = tau & 511;
        const int bjt = tau >> 9;

        if (bjt != cur_bjt) {
            __syncthreads();     // drain readers of old ys
            const float4* yg = (const float4*)(y + ((size_t)(b * NN + jt * 128)) * 64);
            for (int idx = tid; idx < 128 * 16; idx += TPB) {
                int rr = idx >> 4, gg = idx & 15;
                float4 v = yg[rr * 16 + gg];
                float* dst = s + OFF_YS + rr * 68 + gg * 4;
                dst[0] = v.x; dst[1] = v.y; dst[2] = v.z; dst[3] = v.w;
            }
            cur_bjt = bjt;
            __syncthreads();
        }

        // ---- diff^2 -> DH strip (warp-private rows m16..m16+15) ----
        {
            const float4* xg = (const float4*)(x + ((size_t)(b * NN + i)) * 64 + qc * 16);
            float4 xv[4];
            #pragma unroll
            for (int q = 0; q < 4; q++) xv[q] = xg[q];
            #pragma unroll
            for (int rr = 0; rr < 2; rr++) {
                int row = m16 + qr + rr * 8;
                const float4* yrow = (const float4*)(s + OFF_YS + row * 68 + qc * 16);
                uint32_t* drow = (uint32_t*)s + OFF_DH + row * 132 + qc * 16;
                #pragma unroll
                for (int q = 0; q < 4; q++) {
                    float4 yv = yrow[q];
                    float d0 = xv[q].x - yv.x, d1 = xv[q].y - yv.y;
                    float d2 = xv[q].z - yv.z, d3 = xv[q].w - yv.w;
                    uint4 w;
                    w.x = cvt_tf32(d0 * d0); w.y = cvt_tf32(d1 * d1);
                    w.z = cvt_tf32(d2 * d2); w.w = cvt_tf32(d3 * d3);
                    *(uint4*)(drow + q * 4) = w;
                }
            }
        }
        __syncwarp();

        float acc[16][4];
        #pragma unroll
        for (int nt = 0; nt < 16; nt++)
            #pragma unroll
            for (int c = 0; c < 4; c++) acc[nt][c] = 0.f;

        // ---- GEMM1: K=64 (8 k-steps), N=128 (8 nt-pairs) ----
        #pragma unroll
        for (int k = 0; k < 8; k++) {
            uint32_t a0, a1, a2, a3;
            ldsm_x4(a0, a1, a2, a3, aA + k * 32);
            #pragma unroll
            for (int p = 0; p < 8; p++) {
                uint32_t b0, b1v, b2v, b3r;
                ldsm_x4(b0, b1v, b2v, b3r, bB1 + p * 4352 + k * 32);
                mma_tf32(acc[2 * p],     a0, a1, a2, a3, b0, b1v);
                mma_tf32(acc[2 * p + 1], a0, a1, a2, a3, b2v, b3r);
            }
        }
        __syncwarp();

        // ---- epilogue1: H = tf32(relu(C1 + tv)), overwrite DH strip ----
        {
            const float* tvb = s + OFF_TV + b * 128;
            #pragma unroll
            for (int nt = 0; nt < 16; nt++) {
                int h0 = nt * 8 + 2 * qc;
                float2 tvv = *(const float2*)(tvb + h0);
                float v0 = fmaxf(acc[nt][0] + tvv.x, 0.f);
                float v1 = fmaxf(acc[nt][1] + tvv.y, 0.f);
                float v2 = fmaxf(acc[nt][2] + tvv.x, 0.f);
                float v3 = fmaxf(acc[nt][3] + tvv.y, 0.f);
                uint2 w01; w01.x = cvt_tf32(v0); w01.y = cvt_tf32(v1);
                uint2 w23; w23.x = cvt_tf32(v2); w23.y = cvt_tf32(v3);
                *(uint2*)((uint32_t*)s + OFF_DH + (m16 + qr) * 132 + h0)     = w01;
                *(uint2*)((uint32_t*)s + OFF_DH + (m16 + 8 + qr) * 132 + h0) = w23;
                acc[nt][0] = 0.f; acc[nt][1] = 0.f; acc[nt][2] = 0.f; acc[nt][3] = 0.f;
            }
        }
        __syncwarp();

        // ---- GEMM2: K=128 (16 k-steps), N=128 ----
        #pragma unroll
        for (int k = 0; k < 16; k++) {
            uint32_t a0, a1, a2, a3;
            ldsm_x4(a0, a1, a2, a3, aA + k * 32);
            #pragma unroll
            for (int p = 0; p < 8; p++) {
                uint32_t b0, b1v, b2v, b3r;
                ldsm_x4(b0, b1v, b2v, b3r, bB2 + p * 8448 + k * 32);
                mma_tf32(acc[2 * p],     a0, a1, a2, a3, b0, b1v);
                mma_tf32(acc[2 * p + 1], a0, a1, a2, a3, b2v, b3r);
            }
        }

        // ---- epilogue2: out = b3 + sum_n relu(C2 + b2)*W3 ----
        {
            float part0 = 0.f, part1 = 0.f;
            #pragma unroll
            for (int nt = 0; nt < 16; nt++) {
                int h0 = nt * 8 + 2 * qc;
                float2 b2v = *(const float2*)(s + OFF_B2S + h0);
                float2 w3v = *(const float2*)(s + OFF_W3S + h0);
                part0 += fmaxf(acc[nt][0] + b2v.x, 0.f) * w3v.x
                       + fmaxf(acc[nt][1] + b2v.y, 0.f) * w3v.y;
                part1 += fmaxf(acc[nt][2] + b2v.x, 0.f) * w3v.x
                       + fmaxf(acc[nt][3] + b2v.y, 0.f) * w3v.y;
            }
            part0 += __shfl_xor_sync(0xffffffff, part0, 1);
            part0 += __shfl_xor_sync(0xffffffff, part0, 2);
            part1 += __shfl_xor_sync(0xffffffff, part1, 1);
            part1 += __shfl_xor_sync(0xffffffff, part1, 2);
            if (qc == 0) {
                size_t obase = ((size_t)(b * NN + i)) * NN + jt * 128 + m16;
                out[obase + qr]     = part0 + b3v;
                out[obase + 8 + qr] = part1 + b3v;
            }
        }
    }
}

extern "C" void kernel_launch(void* const* d_in, const int* in_sizes, int n_in,
                              void* d_out, int out_size)
{
    const float* x  = (const float*)d_in[0];
    const float* y  = (const float*)d_in[1];
    const float* t  = (const float*)d_in[2];
    const float* W1 = (const float*)d_in[3];
    const float* b1 = (const float*)d_in[4];
    const float* W2 = (const float*)d_in[5];
    const float* b2 = (const float*)d_in[6];
    const float* W3 = (const float*)d_in[7];
    const float* b3 = (const float*)d_in[8];
    float* out = (float*)d_out;

    const int smem_bytes = SMEM_FLOATS * sizeof(float);
    cudaFuncSetAttribute(pairmlp_mma,
                         cudaFuncAttributeMaxDynamicSharedMemorySize, smem_bytes);
    pairmlp_mma<<<GRID, TPB, smem_bytes>>>(x, y, t, W1, b1, W2, b2, W3, b3, out);
}